// round 2
// baseline (speedup 1.0000x reference)
#include <cuda_runtime.h>
#include <math.h>

#define NN 128
#define PITCH 129
#define BATCH 512
#define NPAIRS 8128
#define NTHREADS 1024
#define SEG 16            // NN / 8 segments
#define TSTEPS 10

struct __align__(16) Smem {
  float2 DW[NN * PITCH];   // (d,w) then converted to (w*d, w); symmetric
  float  BG[NN * PITCH];   // Gram matrix (deflated in place); symmetric
  float4 Xs[NN];           // coordinates (x,y,z,0)
  float4 part[7 * NN];     // cross-warp partial sums (h_d = 1..7)
  unsigned bits[NN * 4];   // adjacency bitmask, 4 words/row
  float  rs[NN];           // row sums of D^2
  float  u[NN];            // power-iteration vector
  float  scal[8];          // 0:invN 1:M*invN^2 2:0.4/S 4:bcast scalar
  int    icnt[4];          // 0: sum(adj)
};

__device__ __forceinline__ float softplus_f(float x) {
  return fmaxf(x, 0.0f) + log1pf(__expf(-fabsf(x)));
}

__global__ void __launch_bounds__(NTHREADS, 1)
ts_gcn_kernel(const float* __restrict__ edge_pred,
              const int*   __restrict__ adj,
              const float* __restrict__ d_init,
              const float* __restrict__ u_init,
              const float* __restrict__ x_noise,
              float*       __restrict__ out)
{
  extern __shared__ __align__(16) char smem_raw[];
  Smem* sm = reinterpret_cast<Smem*>(smem_raw);
  const int b   = blockIdx.x;
  const int tid = threadIdx.x;
  const int i_d = tid & (NN - 1);   // row owned in row-parallel phases
  const int h_d = tid >> 7;         // j-segment (0..7), 16 cols each
  const int j0  = h_d * SEG;
  const float d0 = __ldg(d_init);

  const float2* epb  = reinterpret_cast<const float2*>(edge_pred) + (size_t)b * NN * NN;
  const int*    adjb = adj + (size_t)b * NN * NN;

  // ---------------- Phase A1: stage raw edge_pred into SMEM (coalesced) ----
  if (tid == 0) sm->icnt[0] = 0;
  if (tid < NN * 4) sm->bits[tid] = 0u;
  for (int idx = tid; idx < NN * NN; idx += NTHREADS)
    sm->DW[(idx >> 7) * PITCH + (idx & (NN - 1))] = epb[idx];
  __syncthreads();

  // ---------------- Phase A2: symmetrize + softplus + adj mask (upper tri) -
  for (int p = tid; p < NPAIRS; p += NTHREADS) {
    int i = (int)(0.5f * (255.0f - sqrtf(65025.0f - 8.0f * (float)p)));
    while ((((i + 1) * (255 - (i + 1))) >> 1) <= p) ++i;
    while (((i * (255 - i)) >> 1) > p) --i;
    int j = i + 1 + (p - ((i * (255 - i)) >> 1));
    float2 e1 = sm->DW[i * PITCH + j];
    float2 e2 = sm->DW[j * PITCH + i];
    int a = adjb[i * NN + j];
    float2 dw = make_float2(0.0f, 0.0f);
    if (a) {
      dw.x = softplus_f(d0 + e1.x + e2.x);
      dw.y = softplus_f(d0 + e1.y + e2.y);
      atomicOr(&sm->bits[(i << 2) + (j >> 5)], 1u << (j & 31));
      atomicOr(&sm->bits[(j << 2) + (i >> 5)], 1u << (i & 31));
    }
    sm->DW[i * PITCH + j] = dw;
    sm->DW[j * PITCH + i] = dw;
  }
  if (tid < NN) sm->DW[tid * PITCH + tid] = make_float2(0.0f, 0.0f);
  __syncthreads();

  // ---------------- Phase B: S = sum(mask), row sums of D^2 ---------------
  if (tid < NN * 4) {
    int c = __popc(sm->bits[tid]);
    #pragma unroll
    for (int o = 16; o; o >>= 1) c += __shfl_xor_sync(0xffffffffu, c, o);
    if ((tid & 31) == 0) atomicAdd(&sm->icnt[0], c);
  }
  {
    float rpart = 0.0f;
    const float2* col = sm->DW + j0 * PITCH + i_d;   // symmetric, coalesced
    #pragma unroll
    for (int jj = 0; jj < SEG; ++jj) {
      float d = col[jj * PITCH].x;
      rpart = fmaf(d, d, rpart);
    }
    if (h_d) sm->part[(h_d - 1) * NN + i_d].x = rpart;
    __syncthreads();
    if (h_d == 0) {
      #pragma unroll
      for (int r = 0; r < 7; ++r) rpart += sm->part[r * NN + i_d].x;
      sm->rs[i_d] = rpart;
    }
  }
  __syncthreads();
  if (tid < 32) {
    float m = sm->rs[tid] + sm->rs[tid + 32] + sm->rs[tid + 64] + sm->rs[tid + 96];
    #pragma unroll
    for (int o = 16; o; o >>= 1) m += __shfl_xor_sync(0xffffffffu, m, o);
    if (tid == 0) {
      float Nmol = 1.0f + (float)(__popc(sm->bits[0]) + __popc(sm->bits[1]) +
                                  __popc(sm->bits[2]) + __popc(sm->bits[3]));
      float invN = 1.0f / Nmol;
      sm->scal[0] = invN;
      sm->scal[1] = m * invN * invN;          // D_mean term
      float S = 128.0f + (float)sm->icnt[0];  // sum(mask)
      sm->scal[2] = 0.4f / S;                 // 4*STEP_EPS / S
    }
  }
  __syncthreads();

  // ---------------- Phase B2: build Gram matrix BG (coalesced transposed) --
  {
    float invN = sm->scal[0], Moff = sm->scal[1];
    unsigned wb = sm->bits[(i_d << 2) + (j0 >> 5)];
    float rsi = sm->rs[i_d];
    #pragma unroll
    for (int jj = 0; jj < SEG; ++jj) {
      int j = j0 + jj;
      float d = sm->DW[j * PITCH + i_d].x;     // symmetric read, coalesced
      bool m = (((wb >> (j & 31)) & 1u) != 0u) || (j == i_d);
      float v = -0.5f * (fmaf(d, d, Moff) - (rsi + sm->rs[j]) * invN);
      sm->BG[j * PITCH + i_d] = m ? v : 0.0f;  // symmetric write, coalesced
    }
  }
  if (tid < NN) {
    sm->u[tid] = u_init[((size_t)b * NN + tid) * 3];
    sm->Xs[tid].w = 0.0f;
  }
  __syncthreads();

  // ---------------- Phase A3: convert DW -> (w*d, w) in place --------------
  // (no race: each element read+written by one thread; first use is Phase D,
  //  separated by many barriers)
  for (int idx = tid; idx < NN * NN; idx += NTHREADS) {
    float2* p = &sm->DW[(idx >> 7) * PITCH + (idx & (NN - 1))];
    float2 e = *p;
    *p = make_float2(e.x * e.y, e.y);
  }

  // ---------------- Phase C: rank-3 power iteration with deflation ---------
  for (int k = 0; k < 3; ++k) {
    if (k) {
      __syncthreads();
      if (tid < NN) sm->u[tid] = u_init[((size_t)b * NN + tid) * 3 + k];
    }
    for (int it = 0; it < 10; ++it) {
      __syncthreads();
      if (tid < 32) {
        float s = 0.0f;
        #pragma unroll
        for (int r = 0; r < 4; ++r) { float v = sm->u[tid + r * 32]; s = fmaf(v, v, s); }
        #pragma unroll
        for (int o = 16; o; o >>= 1) s += __shfl_xor_sync(0xffffffffu, s, o);
        if (tid == 0) sm->scal[4] = 1.0f / fmaxf(sqrtf(s), 0.001f);
      }
      __syncthreads();
      float acc = 0.0f;
      {
        const float* bgcol = sm->BG + j0 * PITCH + i_d;  // symmetric, coalesced
        const float* useg  = sm->u + j0;
        #pragma unroll
        for (int jj = 0; jj < SEG; ++jj) acc = fmaf(bgcol[jj * PITCH], useg[jj], acc);
      }
      if (h_d) sm->part[(h_d - 1) * NN + i_d].x = acc;
      __syncthreads();
      if (h_d == 0) {
        #pragma unroll
        for (int r = 0; r < 7; ++r) acc += sm->part[r * NN + i_d].x;
        sm->u[i_d] = acc * sm->scal[4];   // A @ (u/|u|)
      }
    }
    __syncthreads();
    if (tid < 32) {
      float s = 0.0f;
      #pragma unroll
      for (int r = 0; r < 4; ++r) { float v = sm->u[tid + r * 32]; s = fmaf(v, v, s); }
      #pragma unroll
      for (int o = 16; o; o >>= 1) s += __shfl_xor_sync(0xffffffffu, s, o);
      if (tid == 0) sm->scal[4] = rsqrtf(sqrtf(s + 0.01f)); // (eig+0.01)^-0.25
    }
    __syncthreads();
    if (tid < NN) {
      float uk = sm->u[tid] * sm->scal[4];
      sm->u[tid] = uk;
      reinterpret_cast<float*>(&sm->Xs[tid])[k] =
          uk + x_noise[((size_t)b * NN + tid) * 3 + k];
    }
    __syncthreads();
    if (k < 2) {  // deflate: BG -= u u^T (transposed write, still a bijection)
      float ui = sm->u[i_d];
      float* bgcol = sm->BG + j0 * PITCH + i_d;
      const float* useg = sm->u + j0;
      #pragma unroll
      for (int jj = 0; jj < SEG; ++jj)
        bgcol[jj * PITCH] = fmaf(-ui, useg[jj], bgcol[jj * PITCH]);
    }
  }
  __syncthreads();

  // ---------------- Phase D: 10 gradient-descent steps ---------------------
  const float c = sm->scal[2];   // 0.4/S
  for (int ts = 0; ts < TSTEPS; ++ts) {
    float alpha = 0.1f + 4.9f * ((float)(TSTEPS - ts) * 0.1f);
    float4 xi = sm->Xs[i_d];
    float ax = 0.0f, ay = 0.0f, az = 0.0f;
    {
      const float2* dwcol = sm->DW + j0 * PITCH + i_d;  // symmetric, coalesced
      const float4* xrow  = sm->Xs + j0;
      #pragma unroll 8
      for (int jj = 0; jj < SEG; ++jj) {
        float4 xj = xrow[jj];                 // broadcast across warp
        float2 dw = dwcol[jj * PITCH];        // (w*d, w)
        float dx = xi.x - xj.x;
        float dy = xi.y - xj.y;
        float dz = xi.z - xj.z;
        float s  = fmaf(dx, dx, fmaf(dy, dy, fmaf(dz, dz, 0.01f)));
        float rinv = rsqrtf(s);
        float coef = fmaf(dw.x, rinv, -dw.y); // w*(d/Dx - 1)
        ax = fmaf(coef, dx, ax);
        ay = fmaf(coef, dy, ay);
        az = fmaf(coef, dz, az);
      }
    }
    if (h_d) sm->part[(h_d - 1) * NN + i_d] = make_float4(ax, ay, az, 0.0f);
    __syncthreads();
    if (h_d == 0) {
      #pragma unroll
      for (int r = 0; r < 7; ++r) {
        float4 p = sm->part[r * NN + i_d];
        ax += p.x; ay += p.y; az += p.z;
      }
      float gx = ax * c, gy = ay * c, gz = az * c;   // dx = -eps*grad
      float sp = sqrtf(fmaf(gx, gx, fmaf(gy, gy, fmaf(gz, gz, 0.001f))));
      float sc = alpha * tanhf(sp / alpha) / sp;
      xi.x = fmaf(gx, sc, xi.x);
      xi.y = fmaf(gy, sc, xi.y);
      xi.z = fmaf(gz, sc, xi.z);
      sm->Xs[i_d] = xi;
    }
    __syncthreads();
  }

  // ---------------- Phase E: output = adj * distances(X) -------------------
  float* outb = out + (size_t)b * NN * NN;
  for (int g = tid; g < (NN * NN) / 4; g += NTHREADS) {
    int i  = g >> 5;
    int jb = (g & 31) * 4;
    float4 xi = sm->Xs[i];
    unsigned wb = sm->bits[(i << 2) + (jb >> 5)];
    float4 r;
    #pragma unroll
    for (int m = 0; m < 4; ++m) {
      int j = jb + m;
      float4 xj = sm->Xs[j];
      float dx = xi.x - xj.x, dy = xi.y - xj.y, dz = xi.z - xj.z;
      float s = fmaf(dx, dx, fmaf(dy, dy, fmaf(dz, dz, 0.01f)));
      float v = ((wb >> (j & 31)) & 1u) ? sqrtf(s) : 0.0f;
      reinterpret_cast<float*>(&r)[m] = v;
    }
    reinterpret_cast<float4*>(outb)[g] = r;
  }
}

extern "C" void kernel_launch(void* const* d_in, const int* in_sizes, int n_in,
                              void* d_out, int out_size) {
  const float* edge_pred = (const float*)d_in[0];
  const int*   adj       = (const int*)  d_in[1];
  const float* d_init    = (const float*)d_in[2];
  const float* u_init    = (const float*)d_in[3];
  const float* x_noise   = (const float*)d_in[4];
  float* out = (float*)d_out;

  size_t smem = sizeof(Smem);
  cudaFuncSetAttribute(ts_gcn_kernel,
                       cudaFuncAttributeMaxDynamicSharedMemorySize, (int)smem);
  ts_gcn_kernel<<<BATCH, NTHREADS, smem>>>(edge_pred, adj, d_init, u_init,
                                           x_noise, out);
}

// round 4
// speedup vs baseline: 1.5305x; 1.5305x over previous
#include <cuda_runtime.h>
#include <math.h>

#define NN 128
#define PITCHD 130   // float2 pitch: conflict-free LDS.128 row reads
#define BATCH 512
#define NPAIRS 8128
#define NT 512
#define SEGJ 32
#define TSTEPS 10

struct __align__(16) Smem {
  float2 DW[NN * PITCHD];   // (d,w) pairs, row-major, symmetric
  float4 Xs[NN];            // coordinates
  float4 part[3 * NN];      // cross-group partial sums
  unsigned bits[NN * 4];    // adjacency bitmask
  float rs[NN];             // row sums of D^2
  float u[NN];              // power-iteration vector
  float scal[8];
  int icnt[4];
};

__device__ __forceinline__ float softplus_f(float x) {
  return fmaxf(x, 0.0f) + log1pf(__expf(-fabsf(x)));
}

__global__ void __launch_bounds__(NT, 1)
ts_gcn_kernel(const float* __restrict__ edge_pred,
              const int*   __restrict__ adj,
              const float* __restrict__ d_init,
              const float* __restrict__ u_init,
              const float* __restrict__ x_noise,
              float*       __restrict__ out)
{
  extern __shared__ __align__(16) char smem_raw[];
  Smem* sm = reinterpret_cast<Smem*>(smem_raw);
  const int b    = blockIdx.x;
  const int tid  = threadIdx.x;
  const int lane = tid & 31;
  const int wid  = tid >> 5;
  const int i_d  = tid & (NN - 1);
  const int g    = tid >> 7;        // j-group 0..3
  const int j0   = g * SEGJ;
  const float d0 = __ldg(d_init);

  const float2* epb  = reinterpret_cast<const float2*>(edge_pred) + (size_t)b * NN * NN;
  const int*    adjb = adj + (size_t)b * NN * NN;

  if (tid == 0) sm->icnt[0] = 0;

  // ---- A1: stage raw edge_pred (coalesced LDG.64 -> STS) -------------------
  #pragma unroll
  for (int v = 0; v < 32; ++v) {
    int idx = v * NT + tid;
    sm->DW[(idx >> 7) * PITCHD + (idx & (NN - 1))] = epb[idx];
  }
  // ---- A1b: adjacency bits via ballot (no atomics) --------------------------
  #pragma unroll
  for (int v = 0; v < 32; ++v) {
    int word = v * 16 + wid;                 // 512 words total
    int i = word >> 2, q = word & 3;
    int a = adjb[i * NN + q * 32 + lane];    // coalesced 128B per warp
    unsigned m = __ballot_sync(0xffffffffu, a != 0);
    if (lane == 0) sm->bits[word] = m;
  }
  __syncthreads();

  // ---- A2: symmetrize + softplus over upper triangle (closed-form fold) ----
  #pragma unroll
  for (int v = 0; v < 16; ++v) {
    int p = v * NT + tid;                    // p in [0, 8192)
    if (p < NPAIRS) {                        // GUARD: 8192 > 8128 slots
      int r = p / 127, c = p - r * 127;
      int i, j;
      if (c >= r) { i = r; j = c + 1; }
      else        { i = 127 - r; j = 127 - c; }
      unsigned on = (sm->bits[(i << 2) + (j >> 5)] >> (j & 31)) & 1u;
      float2 e1 = sm->DW[i * PITCHD + j];
      float2 e2 = sm->DW[j * PITCHD + i];
      float2 dw = make_float2(0.0f, 0.0f);
      if (on) {
        dw.x = softplus_f(d0 + e1.x + e2.x);
        dw.y = softplus_f(d0 + e1.y + e2.y);
      }
      sm->DW[i * PITCHD + j] = dw;
      sm->DW[j * PITCHD + i] = dw;
    }
  }
  if (tid < NN) sm->DW[tid * PITCHD + tid] = make_float2(0.0f, 0.0f);
  __syncthreads();

  // ---- B: sum(adj) + row sums of D^2 ---------------------------------------
  {
    int cbit = __popc(sm->bits[tid]);        // NT == 512 words, one each
    #pragma unroll
    for (int o = 16; o; o >>= 1) cbit += __shfl_xor_sync(0xffffffffu, cbit, o);
    if (lane == 0) atomicAdd(&sm->icnt[0], cbit);
  }
  {
    float rp = 0.0f;
    const float4* drow = reinterpret_cast<const float4*>(sm->DW + i_d * PITCHD + j0);
    #pragma unroll
    for (int t = 0; t < 16; ++t) {
      float4 q = drow[t];                    // (d,w,d,w)
      rp = fmaf(q.x, q.x, rp);
      rp = fmaf(q.z, q.z, rp);
    }
    if (g) sm->part[(g - 1) * NN + i_d].x = rp;
    __syncthreads();
    if (g == 0) {
      rp += sm->part[i_d].x + sm->part[NN + i_d].x + sm->part[2 * NN + i_d].x;
      sm->rs[i_d] = rp;
    }
  }
  __syncthreads();
  if (tid < 32) {
    float m = sm->rs[tid] + sm->rs[tid + 32] + sm->rs[tid + 64] + sm->rs[tid + 96];
    #pragma unroll
    for (int o = 16; o; o >>= 1) m += __shfl_xor_sync(0xffffffffu, m, o);
    if (tid == 0) {
      float Nmol = 1.0f + (float)(__popc(sm->bits[0]) + __popc(sm->bits[1]) +
                                  __popc(sm->bits[2]) + __popc(sm->bits[3]));
      float invN = 1.0f / Nmol;
      sm->scal[0] = invN;
      sm->scal[1] = m * invN * invN;
      float S = 128.0f + (float)sm->icnt[0];
      sm->scal[2] = 0.4f / S;                // 4*STEP_EPS / sum(mask)
    }
  }
  __syncthreads();

  // ---- B2: Gram matrix directly into REGISTERS -----------------------------
  float bg[SEGJ];
  {
    float invN = sm->scal[0], Moff = sm->scal[1];
    float rsi = sm->rs[i_d];
    unsigned wb = sm->bits[(i_d << 2) + (j0 >> 5)];
    const float4* drow = reinterpret_cast<const float4*>(sm->DW + i_d * PITCHD + j0);
    const float4* rsj  = reinterpret_cast<const float4*>(sm->rs + j0);
    #pragma unroll
    for (int t = 0; t < 8; ++t) {
      float4 rq = rsj[t];
      float4 q0 = drow[2 * t], q1 = drow[2 * t + 1];
      float dv[4] = {q0.x, q0.z, q1.x, q1.z};
      float rv[4] = {rq.x, rq.y, rq.z, rq.w};
      #pragma unroll
      for (int m = 0; m < 4; ++m) {
        int jj = 4 * t + m;
        int j = j0 + jj;
        bool on = (((wb >> jj) & 1u) != 0u) || (j == i_d);
        float val = -0.5f * (fmaf(dv[m], dv[m], Moff) - (rsi + rv[m]) * invN);
        bg[jj] = on ? val : 0.0f;
      }
    }
  }

  // ---- C: rank-3 power iteration, BG in regs, redundant norms --------------
  for (int k = 0; k < 3; ++k) {
    __syncthreads();
    if (tid < NN) sm->u[tid] = u_init[((size_t)b * NN + tid) * 3 + k];
    __syncthreads();
    for (int it = 0; it < 10; ++it) {
      // redundant per-warp norm of current u
      float4 uv = reinterpret_cast<const float4*>(sm->u)[lane];
      float s = fmaf(uv.x, uv.x, fmaf(uv.y, uv.y, fmaf(uv.z, uv.z, uv.w * uv.w)));
      #pragma unroll
      for (int o = 16; o; o >>= 1) s += __shfl_xor_sync(0xffffffffu, s, o);
      float invn = 1.0f / fmaxf(sqrtf(s), 0.001f);
      // matvec on register BG
      float acc = 0.0f;
      const float4* useg = reinterpret_cast<const float4*>(sm->u + j0);
      #pragma unroll
      for (int t = 0; t < 8; ++t) {
        float4 uq = useg[t];
        acc = fmaf(bg[4 * t + 0], uq.x, acc);
        acc = fmaf(bg[4 * t + 1], uq.y, acc);
        acc = fmaf(bg[4 * t + 2], uq.z, acc);
        acc = fmaf(bg[4 * t + 3], uq.w, acc);
      }
      if (g) sm->part[(g - 1) * NN + i_d].x = acc;
      __syncthreads();
      if (g == 0) {
        acc += sm->part[i_d].x + sm->part[NN + i_d].x + sm->part[2 * NN + i_d].x;
        sm->u[i_d] = acc * invn;             // (A @ u) / |u|
      }
      __syncthreads();
    }
    // eigen-normalize (redundant per warp)
    float4 uv = reinterpret_cast<const float4*>(sm->u)[lane];
    float s = fmaf(uv.x, uv.x, fmaf(uv.y, uv.y, fmaf(uv.z, uv.z, uv.w * uv.w)));
    #pragma unroll
    for (int o = 16; o; o >>= 1) s += __shfl_xor_sync(0xffffffffu, s, o);
    float sc4 = rsqrtf(sqrtf(s + 0.01f));    // (eig_sq + 0.01)^-0.25
    __syncthreads();                          // all reads of u done
    if (tid < NN) {
      float uk = sm->u[tid] * sc4;
      sm->u[tid] = uk;
      reinterpret_cast<float*>(&sm->Xs[tid])[k] =
          uk + x_noise[((size_t)b * NN + tid) * 3 + k];
      if (k == 0) sm->Xs[tid].w = 0.0f;
    }
    __syncthreads();
    if (k < 2) {                              // deflate BG in regs
      float ui = sm->u[i_d];
      const float4* useg = reinterpret_cast<const float4*>(sm->u + j0);
      #pragma unroll
      for (int t = 0; t < 8; ++t) {
        float4 uq = useg[t];
        bg[4 * t + 0] = fmaf(-ui, uq.x, bg[4 * t + 0]);
        bg[4 * t + 1] = fmaf(-ui, uq.y, bg[4 * t + 1]);
        bg[4 * t + 2] = fmaf(-ui, uq.z, bg[4 * t + 2]);
        bg[4 * t + 3] = fmaf(-ui, uq.w, bg[4 * t + 3]);
      }
    }
  }

  // ---- preload (w*d, w) into registers for all 10 steps ---------------------
  float2 dwr[SEGJ];
  {
    const float4* drow = reinterpret_cast<const float4*>(sm->DW + i_d * PITCHD + j0);
    #pragma unroll
    for (int t = 0; t < 16; ++t) {
      float4 q = drow[t];
      dwr[2 * t]     = make_float2(q.x * q.y, q.y);
      dwr[2 * t + 1] = make_float2(q.z * q.w, q.w);
    }
  }
  const float cc = sm->scal[2];

  // ---- D: 10 gradient-descent steps -----------------------------------------
  for (int ts = 0; ts < TSTEPS; ++ts) {
    float alpha = 0.1f + 4.9f * ((float)(TSTEPS - ts) * 0.1f);
    float4 xi = sm->Xs[i_d];
    float ax = 0.0f, ay = 0.0f, az = 0.0f;
    const float4* xrow = sm->Xs + j0;
    #pragma unroll
    for (int jj = 0; jj < SEGJ; ++jj) {
      float4 xj = xrow[jj];                  // broadcast LDS.128
      float dx = xi.x - xj.x;
      float dy = xi.y - xj.y;
      float dz = xi.z - xj.z;
      float s = fmaf(dx, dx, fmaf(dy, dy, fmaf(dz, dz, 0.01f)));
      float rinv = rsqrtf(s);
      float coef = fmaf(dwr[jj].x, rinv, -dwr[jj].y);  // w*(d/Dx - 1)
      ax = fmaf(coef, dx, ax);
      ay = fmaf(coef, dy, ay);
      az = fmaf(coef, dz, az);
    }
    if (g) sm->part[(g - 1) * NN + i_d] = make_float4(ax, ay, az, 0.0f);
    __syncthreads();
    if (g == 0) {
      float4 p1 = sm->part[i_d], p2 = sm->part[NN + i_d], p3 = sm->part[2 * NN + i_d];
      float gx = (ax + p1.x + p2.x + p3.x) * cc;
      float gy = (ay + p1.y + p2.y + p3.y) * cc;
      float gz = (az + p1.z + p2.z + p3.z) * cc;
      float s2 = fmaf(gx, gx, fmaf(gy, gy, fmaf(gz, gz, 0.001f)));
      float inv_sp = rsqrtf(s2);
      float sp = s2 * inv_sp;
      float e = __expf(2.0f * (sp / alpha));
      float th = 1.0f - __fdividef(2.0f, e + 1.0f);   // tanh(sp/alpha)
      float sc = alpha * th * inv_sp;
      xi.x = fmaf(gx, sc, xi.x);
      xi.y = fmaf(gy, sc, xi.y);
      xi.z = fmaf(gz, sc, xi.z);
      sm->Xs[i_d] = xi;
    }
    __syncthreads();
  }

  // ---- E: output = adj * distances(X) ---------------------------------------
  float* outb = out + (size_t)b * NN * NN;
  #pragma unroll
  for (int v = 0; v < 8; ++v) {
    int f = v * NT + tid;                    // float4 index
    int i = f >> 5;
    int jb = (f & 31) * 4;
    float4 xi = sm->Xs[i];
    unsigned wb = sm->bits[(i << 2) + (jb >> 5)];
    float4 r;
    #pragma unroll
    for (int m = 0; m < 4; ++m) {
      int j = jb + m;
      float4 xj = sm->Xs[j];
      float dx = xi.x - xj.x, dy = xi.y - xj.y, dz = xi.z - xj.z;
      float s = fmaf(dx, dx, fmaf(dy, dy, fmaf(dz, dz, 0.01f)));
      float val = ((wb >> (j & 31)) & 1u) ? sqrtf(s) : 0.0f;
      reinterpret_cast<float*>(&r)[m] = val;
    }
    reinterpret_cast<float4*>(outb)[f] = r;
  }
}

extern "C" void kernel_launch(void* const* d_in, const int* in_sizes, int n_in,
                              void* d_out, int out_size) {
  const float* edge_pred = (const float*)d_in[0];
  const int*   adj       = (const int*)  d_in[1];
  const float* d_init    = (const float*)d_in[2];
  const float* u_init    = (const float*)d_in[3];
  const float* x_noise   = (const float*)d_in[4];
  float* out = (float*)d_out;

  size_t smem = sizeof(Smem);
  cudaFuncSetAttribute(ts_gcn_kernel,
                       cudaFuncAttributeMaxDynamicSharedMemorySize, (int)smem);
  ts_gcn_kernel<<<BATCH, NT, smem>>>(edge_pred, adj, d_init, u_init,
                                     x_noise, out);
}

// round 5
// speedup vs baseline: 1.5971x; 1.0435x over previous
#include <cuda_runtime.h>
#include <math.h>

#define NN 128
#define PITCHD 130   // float2 pitch: conflict-free LDS.128 row reads
#define BATCH 512
#define NPAIRS 8128
#define NT 512
#define SEGJ 32
#define TSTEPS 10

struct __align__(16) Smem {
  float2 DW[NN * PITCHD];   // (d,w) pairs, row-major, symmetric
  float4 Xs[NN];            // coordinates, .w = |x|^2
  float4 part[3 * NN];      // cross-group partial sums (x,y,z = sum coef*xj, w = sum coef)
  unsigned bits[NN * 4];    // adjacency bitmask
  float rs[NN];             // row sums of D^2
  float u[NN];              // power-iteration vector
  float scal[8];
  int icnt[4];
};

__device__ __forceinline__ float softplus_f(float x) {
  // softplus = max(x,0) + log(1 + exp(-|x|)); arg of log in (1,2] -> __logf ok
  return fmaxf(x, 0.0f) + __logf(1.0f + __expf(-fabsf(x)));
}

__global__ void __launch_bounds__(NT, 1)
ts_gcn_kernel(const float* __restrict__ edge_pred,
              const int*   __restrict__ adj,
              const float* __restrict__ d_init,
              const float* __restrict__ u_init,
              const float* __restrict__ x_noise,
              float*       __restrict__ out)
{
  extern __shared__ __align__(16) char smem_raw[];
  Smem* sm = reinterpret_cast<Smem*>(smem_raw);
  const int b    = blockIdx.x;
  const int tid  = threadIdx.x;
  const int lane = tid & 31;
  const int wid  = tid >> 5;
  const int i_d  = tid & (NN - 1);
  const int g    = tid >> 7;        // j-group 0..3
  const int j0   = g * SEGJ;
  const float d0 = __ldg(d_init);

  const float2* epb  = reinterpret_cast<const float2*>(edge_pred) + (size_t)b * NN * NN;
  const int*    adjb = adj + (size_t)b * NN * NN;

  if (tid == 0) sm->icnt[0] = 0;

  // ---- A1: stage raw edge_pred (coalesced LDG.64 -> STS) -------------------
  #pragma unroll
  for (int v = 0; v < 32; ++v) {
    int idx = v * NT + tid;
    sm->DW[(idx >> 7) * PITCHD + (idx & (NN - 1))] = epb[idx];
  }
  // ---- A1b: adjacency bits via ballot (no atomics) --------------------------
  #pragma unroll
  for (int v = 0; v < 32; ++v) {
    int word = v * 16 + wid;                 // 512 words total
    int i = word >> 2, q = word & 3;
    int a = adjb[i * NN + q * 32 + lane];    // coalesced 128B per warp
    unsigned m = __ballot_sync(0xffffffffu, a != 0);
    if (lane == 0) sm->bits[word] = m;
  }
  __syncthreads();

  // ---- A2: symmetrize + softplus over upper triangle (closed-form fold) ----
  #pragma unroll
  for (int v = 0; v < 16; ++v) {
    int p = v * NT + tid;                    // p in [0, 8192)
    if (p < NPAIRS) {                        // guard: 8192 > 8128 slots
      int r = p / 127, c = p - r * 127;
      int i, j;
      if (c >= r) { i = r; j = c + 1; }
      else        { i = 127 - r; j = 127 - c; }
      unsigned on = (sm->bits[(i << 2) + (j >> 5)] >> (j & 31)) & 1u;
      float2 e1 = sm->DW[i * PITCHD + j];
      float2 e2 = sm->DW[j * PITCHD + i];
      float2 dw = make_float2(0.0f, 0.0f);
      if (on) {
        dw.x = softplus_f(d0 + e1.x + e2.x);
        dw.y = softplus_f(d0 + e1.y + e2.y);
      }
      sm->DW[i * PITCHD + j] = dw;
      sm->DW[j * PITCHD + i] = dw;
    }
  }
  if (tid < NN) sm->DW[tid * PITCHD + tid] = make_float2(0.0f, 0.0f);
  __syncthreads();

  // ---- B: sum(adj) + row sums of D^2 ---------------------------------------
  {
    int cbit = __popc(sm->bits[tid]);
    #pragma unroll
    for (int o = 16; o; o >>= 1) cbit += __shfl_xor_sync(0xffffffffu, cbit, o);
    if (lane == 0) atomicAdd(&sm->icnt[0], cbit);
  }
  {
    float rp = 0.0f;
    const float4* drow = reinterpret_cast<const float4*>(sm->DW + i_d * PITCHD + j0);
    #pragma unroll
    for (int t = 0; t < 16; ++t) {
      float4 q = drow[t];                    // (d,w,d,w)
      rp = fmaf(q.x, q.x, rp);
      rp = fmaf(q.z, q.z, rp);
    }
    if (g) sm->part[(g - 1) * NN + i_d].x = rp;
    __syncthreads();
    if (g == 0) {
      rp += sm->part[i_d].x + sm->part[NN + i_d].x + sm->part[2 * NN + i_d].x;
      sm->rs[i_d] = rp;
    }
  }
  __syncthreads();
  if (tid < 32) {
    float m = sm->rs[tid] + sm->rs[tid + 32] + sm->rs[tid + 64] + sm->rs[tid + 96];
    #pragma unroll
    for (int o = 16; o; o >>= 1) m += __shfl_xor_sync(0xffffffffu, m, o);
    if (tid == 0) {
      float Nmol = 1.0f + (float)(__popc(sm->bits[0]) + __popc(sm->bits[1]) +
                                  __popc(sm->bits[2]) + __popc(sm->bits[3]));
      float invN = 1.0f / Nmol;
      sm->scal[0] = invN;
      sm->scal[1] = m * invN * invN;
      float S = 128.0f + (float)sm->icnt[0];
      sm->scal[2] = 0.4f / S;                // 4*STEP_EPS / sum(mask)
    }
  }
  __syncthreads();

  // ---- B2: Gram matrix directly into REGISTERS -----------------------------
  float bg[SEGJ];
  {
    float invN = sm->scal[0], Moff = sm->scal[1];
    float rsi = sm->rs[i_d];
    unsigned wb = sm->bits[(i_d << 2) + (j0 >> 5)];
    const float4* drow = reinterpret_cast<const float4*>(sm->DW + i_d * PITCHD + j0);
    const float4* rsj  = reinterpret_cast<const float4*>(sm->rs + j0);
    #pragma unroll
    for (int t = 0; t < 8; ++t) {
      float4 rq = rsj[t];
      float4 q0 = drow[2 * t], q1 = drow[2 * t + 1];
      float dv[4] = {q0.x, q0.z, q1.x, q1.z};
      float rv[4] = {rq.x, rq.y, rq.z, rq.w};
      #pragma unroll
      for (int m = 0; m < 4; ++m) {
        int jj = 4 * t + m;
        int j = j0 + jj;
        bool on = (((wb >> jj) & 1u) != 0u) || (j == i_d);
        float val = -0.5f * (fmaf(dv[m], dv[m], Moff) - (rsi + rv[m]) * invN);
        bg[jj] = on ? val : 0.0f;
      }
    }
  }

  // ---- C: rank-3 power iteration, BG in regs, redundant norms --------------
  for (int k = 0; k < 3; ++k) {
    __syncthreads();
    if (tid < NN) sm->u[tid] = u_init[((size_t)b * NN + tid) * 3 + k];
    __syncthreads();
    for (int it = 0; it < 10; ++it) {
      float4 uv = reinterpret_cast<const float4*>(sm->u)[lane];
      float s = fmaf(uv.x, uv.x, fmaf(uv.y, uv.y, fmaf(uv.z, uv.z, uv.w * uv.w)));
      #pragma unroll
      for (int o = 16; o; o >>= 1) s += __shfl_xor_sync(0xffffffffu, s, o);
      float invn = 1.0f / fmaxf(sqrtf(s), 0.001f);
      float acc = 0.0f;
      const float4* useg = reinterpret_cast<const float4*>(sm->u + j0);
      #pragma unroll
      for (int t = 0; t < 8; ++t) {
        float4 uq = useg[t];
        acc = fmaf(bg[4 * t + 0], uq.x, acc);
        acc = fmaf(bg[4 * t + 1], uq.y, acc);
        acc = fmaf(bg[4 * t + 2], uq.z, acc);
        acc = fmaf(bg[4 * t + 3], uq.w, acc);
      }
      if (g) sm->part[(g - 1) * NN + i_d].x = acc;
      __syncthreads();
      if (g == 0) {
        acc += sm->part[i_d].x + sm->part[NN + i_d].x + sm->part[2 * NN + i_d].x;
        sm->u[i_d] = acc * invn;
      }
      __syncthreads();
    }
    float4 uv = reinterpret_cast<const float4*>(sm->u)[lane];
    float s = fmaf(uv.x, uv.x, fmaf(uv.y, uv.y, fmaf(uv.z, uv.z, uv.w * uv.w)));
    #pragma unroll
    for (int o = 16; o; o >>= 1) s += __shfl_xor_sync(0xffffffffu, s, o);
    float sc4 = rsqrtf(sqrtf(s + 0.01f));    // (eig_sq + 0.01)^-0.25
    __syncthreads();
    if (tid < NN) {
      float uk = sm->u[tid] * sc4;
      sm->u[tid] = uk;
      reinterpret_cast<float*>(&sm->Xs[tid])[k] =
          uk + x_noise[((size_t)b * NN + tid) * 3 + k];
    }
    __syncthreads();
    if (k < 2) {
      float ui = sm->u[i_d];
      const float4* useg = reinterpret_cast<const float4*>(sm->u + j0);
      #pragma unroll
      for (int t = 0; t < 8; ++t) {
        float4 uq = useg[t];
        bg[4 * t + 0] = fmaf(-ui, uq.x, bg[4 * t + 0]);
        bg[4 * t + 1] = fmaf(-ui, uq.y, bg[4 * t + 1]);
        bg[4 * t + 2] = fmaf(-ui, uq.z, bg[4 * t + 2]);
        bg[4 * t + 3] = fmaf(-ui, uq.w, bg[4 * t + 3]);
      }
    }
  }
  // finalize Xs.w = |x|^2
  if (tid < NN) {
    float4 x = sm->Xs[tid];
    x.w = fmaf(x.x, x.x, fmaf(x.y, x.y, x.z * x.z));
    sm->Xs[tid] = x;
  }

  // ---- preload (w*d, w) into registers for all 10 steps ---------------------
  float2 dwr[SEGJ];
  {
    const float4* drow = reinterpret_cast<const float4*>(sm->DW + i_d * PITCHD + j0);
    #pragma unroll
    for (int t = 0; t < 16; ++t) {
      float4 q = drow[t];
      dwr[2 * t]     = make_float2(q.x * q.y, q.y);
      dwr[2 * t + 1] = make_float2(q.z * q.w, q.w);
    }
  }
  const float cc = sm->scal[2];
  __syncthreads();

  // ---- D: 10 gradient-descent steps (dot-product form) ----------------------
  for (int ts = 0; ts < TSTEPS; ++ts) {
    float alpha = 0.1f + 4.9f * ((float)(TSTEPS - ts) * 0.1f);
    float4 xi = sm->Xs[i_d];
    float m2x = -2.0f * xi.x, m2y = -2.0f * xi.y, m2z = -2.0f * xi.z;
    float cbase = xi.w + 0.01f;              // |xi|^2 + 0.01
    float cs = 0.0f, ax = 0.0f, ay = 0.0f, az = 0.0f;
    const float4* xrow = sm->Xs + j0;
    #pragma unroll
    for (int jj = 0; jj < SEGJ; ++jj) {
      float4 xj = xrow[jj];                  // broadcast LDS.128
      float t = fmaf(xj.x, m2x, xj.w);       // |xj|^2 - 2 xi.xj (partial)
      t = fmaf(xj.y, m2y, t);
      t = fmaf(xj.z, m2z, t);
      float s = t + cbase;                   // |xi-xj|^2 + 0.01
      float rinv = rsqrtf(s);
      float coef = fmaf(dwr[jj].x, rinv, -dwr[jj].y);  // w*(d/Dx - 1)
      cs += coef;
      ax = fmaf(coef, xj.x, ax);
      ay = fmaf(coef, xj.y, ay);
      az = fmaf(coef, xj.z, az);
    }
    if (g) sm->part[(g - 1) * NN + i_d] = make_float4(ax, ay, az, cs);
    __syncthreads();
    if (g == 0) {
      float4 p1 = sm->part[i_d], p2 = sm->part[NN + i_d], p3 = sm->part[2 * NN + i_d];
      float AX = ax + p1.x + p2.x + p3.x;
      float AY = ay + p1.y + p2.y + p3.y;
      float AZ = az + p1.z + p2.z + p3.z;
      float CS = cs + p1.w + p2.w + p3.w;
      float gx = fmaf(CS, xi.x, -AX) * cc;   // (sum coef*(xi-xj)) * cc
      float gy = fmaf(CS, xi.y, -AY) * cc;
      float gz = fmaf(CS, xi.z, -AZ) * cc;
      float s2 = fmaf(gx, gx, fmaf(gy, gy, fmaf(gz, gz, 0.001f)));
      float inv_sp = rsqrtf(s2);
      float sp = s2 * inv_sp;
      float e = __expf(2.0f * (sp / alpha));
      float th = 1.0f - __fdividef(2.0f, e + 1.0f);   // tanh(sp/alpha)
      float sc = alpha * th * inv_sp;
      xi.x = fmaf(gx, sc, xi.x);
      xi.y = fmaf(gy, sc, xi.y);
      xi.z = fmaf(gz, sc, xi.z);
      xi.w = fmaf(xi.x, xi.x, fmaf(xi.y, xi.y, xi.z * xi.z));
      sm->Xs[i_d] = xi;
    }
    __syncthreads();
  }

  // ---- E: output = adj * distances(X) (exact differences) -------------------
  float* outb = out + (size_t)b * NN * NN;
  #pragma unroll
  for (int v = 0; v < 8; ++v) {
    int f = v * NT + tid;                    // float4 index
    int i = f >> 5;
    int jb = (f & 31) * 4;
    float4 xi = sm->Xs[i];
    unsigned wb = sm->bits[(i << 2) + (jb >> 5)];
    float4 r;
    #pragma unroll
    for (int m = 0; m < 4; ++m) {
      int j = jb + m;
      float4 xj = sm->Xs[j];
      float dx = xi.x - xj.x, dy = xi.y - xj.y, dz = xi.z - xj.z;
      float s = fmaf(dx, dx, fmaf(dy, dy, fmaf(dz, dz, 0.01f)));
      float val = ((wb >> (j & 31)) & 1u) ? sqrtf(s) : 0.0f;
      reinterpret_cast<float*>(&r)[m] = val;
    }
    reinterpret_cast<float4*>(outb)[f] = r;
  }
}

extern "C" void kernel_launch(void* const* d_in, const int* in_sizes, int n_in,
                              void* d_out, int out_size) {
  const float* edge_pred = (const float*)d_in[0];
  const int*   adj       = (const int*)  d_in[1];
  const float* d_init    = (const float*)d_in[2];
  const float* u_init    = (const float*)d_in[3];
  const float* x_noise   = (const float*)d_in[4];
  float* out = (float*)d_out;

  size_t smem = sizeof(Smem);
  cudaFuncSetAttribute(ts_gcn_kernel,
                       cudaFuncAttributeMaxDynamicSharedMemorySize, (int)smem);
  ts_gcn_kernel<<<BATCH, NT, smem>>>(edge_pred, adj, d_init, u_init,
                                     x_noise, out);
}